// round 14
// baseline (speedup 1.0000x reference)
#include <cuda_runtime.h>
#include <cuda_fp16.h>

#define NN 50000
#define EE 500000
#define FF 64
#define HH 4

// ---------------- scratch (device globals; no allocation allowed) ----------------
__device__ __align__(16) __half2 g_projh[(size_t)NN * 128]; // [n][h][f] fp16, 25.6 MB
__device__ __align__(16) float g_sc[NN * 8];                // node scores [rad h0..3, tan h0..3]
__device__ __align__(16) float g_ssum[NN * 8];              // softmax denominators
__device__ __align__(16) float g_ex[(size_t)EE * 8];        // per-edge exp(logit)
__device__ __align__(16) float g_acc[NN * FF];              // init -0.5*psum by proj; REDs on top

__device__ __forceinline__ void red_add_v4(float* p, float4 v) {
    asm volatile("red.global.add.v4.f32 [%0], {%1,%2,%3,%4};"
                 :: "l"(p), "f"(v.x), "f"(v.y), "f"(v.z), "f"(v.w) : "memory");
}

// packed fp32 FMA: d = a*b + c  (2 lanes per instruction, FFMA2)
__device__ __forceinline__ float2 fma2(float2 a, float2 b, float2 c) {
    float2 d;
    asm("fma.rn.f32x2 %0, %1, %2, %3;"
        : "=l"(reinterpret_cast<unsigned long long&>(d))
        : "l"(reinterpret_cast<unsigned long long&>(a)),
          "l"(reinterpret_cast<unsigned long long&>(b)),
          "l"(reinterpret_cast<unsigned long long&>(c)));
    return d;
}

// ---------------- proj: zero ssum; wrtT+weights in smem; GEMM + sc in ONE tile loop --
// proj[n,h,g] = sum_f x[n,f]*w_proj[h,f,g] -> g_projh (fp16); g_acc = -0.5*sum_h proj
// sc[n,i] = sum_f x[n,f]*wrt[i,f],  wrt[i,f] = sum_g w_proj[h,f,g]*score_i[g]
// smem: weights 16384 fl (64KB) + xs[24][64] 1536 fl (6KB) + wrtT[64][8] 512 fl (2KB)
//       = 73728 B = 72KB exactly -> 3 blocks/SM
#define PT 24  // nodes per tile (8 warps x 3 nodes)
__global__ void __launch_bounds__(256, 3)
proj_kernel(const float* __restrict__ x,
            const float* __restrict__ w_proj,
            const float* __restrict__ rs,
            const float* __restrict__ ts) {
    extern __shared__ float sh[];
    float2* wsh2 = (float2*)sh;          // [64][128]: wsh2[f*128 + h*32 + gp]
    float*  xs   = sh + 16384;           // [PT][64]
    float*  wrtT = sh + 16384 + PT * 64; // [64][8]: wrtT[f*8 + i]

    int tid = threadIdx.x;
    int gsz = gridDim.x * blockDim.x;

    // zero softmax denominators (completes before pass1 by stream order)
    for (int j = blockIdx.x * blockDim.x + tid; j < NN * 8; j += gsz) g_ssum[j] = 0.f;

    // weights, transposed to [f][h*32+gp]
    for (int idx = tid; idx < 64 * 128; idx += 256) {
        int f = idx >> 7, p = idx & 127;
        int h = p >> 5, gp = p & 31;
        wsh2[idx] = ((const float2*)w_proj)[h * 2048 + f * 32 + gp];
    }
    // wrtT[f][i] (fp32, accuracy-critical logit path)
    {
        int e = tid, i = e >> 6, f = e & 63;       // 256 threads cover i=0..3
        const float* scv = rs;
        const float* wrow = w_proj + (i & 3) * 4096 + f * 64;
        float s = 0.f;
        #pragma unroll 8
        for (int g = 0; g < 64; g++) s += wrow[g] * scv[(i & 3) * 64 + g];
        wrtT[f * 8 + i] = s;
        // i=4..7 (tangential)
        int i2 = i + 4;
        const float* scv2 = ts;
        float s2 = 0.f;
        #pragma unroll 8
        for (int g = 0; g < 64; g++) s2 += wrow[g] * scv2[(i & 3) * 64 + g];
        wrtT[f * 8 + i2] = s2;
    }

    int pg = tid & 31;       // g-pair column (covers g = 2pg, 2pg+1 of every head)
    int ng = tid >> 5;       // warp id: 3 nodes each
    int nd2 = tid >> 3, i2 = tid & 7;   // sc mapping (threads < 192 active)
    int ntiles = (NN + PT - 1) / PT;

    for (int tile = blockIdx.x; tile < ntiles; tile += gridDim.x) {
        int n0 = tile * PT;
        __syncthreads();   // xs reuse across tiles; first iter: weights/wrtT visible after 2nd sync
        for (int idx = tid; idx < PT * 64; idx += 256) {
            int nd = idx >> 6, f = idx & 63;
            int n = n0 + nd;
            xs[nd * 64 + f] = (n < NN) ? x[n * 64 + f] : 0.f;
        }
        __syncthreads();

        float2 acc[3][4];  // [node j][head h] — pair (2pg,2pg+1)
        #pragma unroll
        for (int j = 0; j < 3; j++)
            #pragma unroll
            for (int h = 0; h < 4; h++) acc[j][h] = make_float2(0.f, 0.f);

        #pragma unroll 4
        for (int f = 0; f < 64; f++) {
            float2 w0 = wsh2[f * 128 + pg];
            float2 w1 = wsh2[f * 128 + 32 + pg];
            float2 w2 = wsh2[f * 128 + 64 + pg];
            float2 w3 = wsh2[f * 128 + 96 + pg];
            #pragma unroll
            for (int j = 0; j < 3; j++) {
                float xv = xs[(ng * 3 + j) * 64 + f];  // warp-broadcast read
                float2 xx = make_float2(xv, xv);
                acc[j][0] = fma2(w0, xx, acc[j][0]);
                acc[j][1] = fma2(w1, xx, acc[j][1]);
                acc[j][2] = fma2(w2, xx, acc[j][2]);
                acc[j][3] = fma2(w3, xx, acc[j][3]);
            }
        }

        #pragma unroll
        for (int j = 0; j < 3; j++) {
            int n = n0 + ng * 3 + j;
            if (n < NN) {
                __half2* op = g_projh + (size_t)n * 128;   // [h*32 + pg]
                op[pg]      = __float22half2_rn(acc[j][0]);
                op[32 + pg] = __float22half2_rn(acc[j][1]);
                op[64 + pg] = __float22half2_rn(acc[j][2]);
                op[96 + pg] = __float22half2_rn(acc[j][3]);
                // g_acc preloaded with -0.5 * sum_h proj (receiver term, head-mean folded)
                float2 ps;
                ps.x = -0.5f * (acc[j][0].x + acc[j][1].x + acc[j][2].x + acc[j][3].x);
                ps.y = -0.5f * (acc[j][0].y + acc[j][1].y + acc[j][2].y + acc[j][3].y);
                ((float2*)g_acc)[(size_t)n * 32 + pg] = ps;
            }
        }

        // node scores (fp32): 192 threads, node nd2, score-index i2
        if (tid < 192) {
            int n2 = n0 + nd2;
            if (n2 < NN) {
                float s = 0.f;
                #pragma unroll 8
                for (int f = 0; f < 64; f++) s += xs[nd2 * 64 + f] * wrtT[f * 8 + i2];
                g_sc[n2 * 8 + i2] = s;
            }
        }
    }
}

// ---------------- edge pass 1: exp(logits), accumulate softmax sums ----------------
__global__ void edge_pass1(const int* __restrict__ ei,
                           const float* __restrict__ elen,
                           const float* __restrict__ rds) {
    int i = blockIdx.x * blockDim.x + threadIdx.x;
    if (i >= EE) return;
    float scale = rds[0];
    int s = ei[i], r = ei[EE + i];
    const float4* scp = (const float4*)g_sc;
    float4 a0 = scp[s * 2], a1 = scp[s * 2 + 1];
    float4 b0 = scp[r * 2], b1 = scp[r * 2 + 1];
    float d = scale * elen[i];
    float4 er, et;
    er.x = __expf(a0.x - b0.x - d); er.y = __expf(a0.y - b0.y - d);
    er.z = __expf(a0.z - b0.z - d); er.w = __expf(a0.w - b0.w - d);
    et.x = __expf(a1.x - b1.x);     et.y = __expf(a1.y - b1.y);
    et.z = __expf(a1.z - b1.z);     et.w = __expf(a1.w - b1.w);
    float4* exp_ptr = (float4*)(g_ex + (size_t)i * 8);
    exp_ptr[0] = er;
    exp_ptr[1] = et;
    red_add_v4(g_ssum + r * 8, er);
    red_add_v4(g_ssum + r * 8 + 4, et);
}

// ---------------- edge pass 2: alpha-weighted scatter of fp16 sender proj ------------
// 8 lanes per edge (4 edges per warp); lane sub handles f-chunk [8sub, 8sub+7] of
// every head via one LDG.128 per head (measured best ~43.5us, unchanged)
__global__ void edge_pass2(const int* __restrict__ ei) {
    int lane = threadIdx.x & 31;
    int warp = (blockIdx.x * blockDim.x + threadIdx.x) >> 5;
    int grp = lane >> 3, sub = lane & 7;
    int e = warp * 4 + grp;
    if (e >= EE) return;
    int s = ei[e], r = ei[EE + e];

    // every lane computes one of the 8 alphas
    float a = __fdividef(g_ex[(size_t)e * 8 + sub], g_ssum[r * 8 + sub]);
    // combined per-head weight = alpha_rad[h] + alpha_tan[h]  (shuffle within 8-lane group)
    const unsigned m = 0xffffffffu;
    float w0 = __shfl_sync(m, a, 0, 8) + __shfl_sync(m, a, 4, 8);
    float w1 = __shfl_sync(m, a, 1, 8) + __shfl_sync(m, a, 5, 8);
    float w2 = __shfl_sync(m, a, 2, 8) + __shfl_sync(m, a, 6, 8);
    float w3 = __shfl_sync(m, a, 3, 8) + __shfl_sync(m, a, 7, 8);

    // fp16 row: 256 halves = 32 uint4; head h occupies uint4 [h*8, h*8+7]
    const uint4* ph = (const uint4*)g_projh + (size_t)s * 32;
    uint4 q0 = ph[sub], q1 = ph[8 + sub], q2 = ph[16 + sub], q3 = ph[24 + sub];

    float v[8];
    #pragma unroll
    for (int k = 0; k < 8; k++) v[k] = 0.f;

    #pragma unroll
    for (int h = 0; h < 4; h++) {
        uint4 q = (h == 0) ? q0 : (h == 1) ? q1 : (h == 2) ? q2 : q3;
        float w = (h == 0) ? w0 : (h == 1) ? w1 : (h == 2) ? w2 : w3;
        float2 c0 = __half22float2(*(const __half2*)&q.x);
        float2 c1 = __half22float2(*(const __half2*)&q.y);
        float2 c2 = __half22float2(*(const __half2*)&q.z);
        float2 c3 = __half22float2(*(const __half2*)&q.w);
        v[0] += w * c0.x; v[1] += w * c0.y;
        v[2] += w * c1.x; v[3] += w * c1.y;
        v[4] += w * c2.x; v[5] += w * c2.y;
        v[6] += w * c3.x; v[7] += w * c3.y;
    }
    // 0.25 = head mean, applied once here
    float4 vA = make_float4(0.25f * v[0], 0.25f * v[1], 0.25f * v[2], 0.25f * v[3]);
    float4 vB = make_float4(0.25f * v[4], 0.25f * v[5], 0.25f * v[6], 0.25f * v[7]);
    float* dst = g_acc + r * 64 + sub * 8;
    red_add_v4(dst, vA);
    red_add_v4(dst + 4, vB);
}

// ---------------- epilogue: msg = flag*g_acc; residual + out-GEMM (f32x2) ------------
// g_acc already holds (scatter - 0.5*psum); flag zeroes isolated nodes.
__global__ void epilogue_kernel(const float* __restrict__ x,
                                const float* __restrict__ w_out,
                                float* __restrict__ out) {
    __shared__ float2 wsh2[64 * 32];     // [f][gp]
    __shared__ float msh[8][4][64];
    int tid = threadIdx.x, lane = tid & 31, wid = tid >> 5;
    for (int idx = tid; idx < 2048; idx += 256) wsh2[idx] = ((const float2*)w_out)[idx];
    __syncthreads();

    int base = (blockIdx.x * 8 + wid) * 4;
    if (base >= NN) return;

    #pragma unroll
    for (int j = 0; j < 4; j++) {
        int n = base + j;
        if (n >= NN) { msh[wid][j][lane] = 0.f; msh[wid][j][lane + 32] = 0.f; continue; }
        float flag = (g_ssum[n * 8] > 0.f) ? 1.f : 0.f;
        #pragma unroll
        for (int k = 0; k < 2; k++) {
            int f = lane + k * 32;
            msh[wid][j][f] = flag * g_acc[n * 64 + f];
        }
    }
    __syncwarp();

    float2 a2[4];
    #pragma unroll
    for (int j = 0; j < 4; j++) {
        int n = base + j;
        a2[j] = (n < NN) ? ((const float2*)x)[n * 32 + lane] : make_float2(0.f, 0.f);
    }
    #pragma unroll 4
    for (int f = 0; f < 64; f++) {
        float2 w = wsh2[f * 32 + lane];
        #pragma unroll
        for (int j = 0; j < 4; j++) {
            float m = msh[wid][j][f];
            a2[j] = fma2(w, make_float2(m, m), a2[j]);
        }
    }
    #pragma unroll
    for (int j = 0; j < 4; j++) {
        int n = base + j;
        if (n < NN) ((float2*)out)[n * 32 + lane] = a2[j];
    }
}

// ---------------- launch ----------------
extern "C" void kernel_launch(void* const* d_in, const int* in_sizes, int n_in,
                              void* d_out, int out_size) {
    const float* x      = (const float*)d_in[0];
    const int*   ei     = (const int*)d_in[1];
    // d_in[2] = edge_vec (unused by reference)
    const float* elen   = (const float*)d_in[3];
    const float* w_proj = (const float*)d_in[4];
    const float* rs     = (const float*)d_in[5];
    const float* ts     = (const float*)d_in[6];
    const float* rds    = (const float*)d_in[7];
    const float* w_out  = (const float*)d_in[8];
    float* out = (float*)d_out;

    // proj smem: 16384 (weights) + 1536 (xs) + 512 (wrtT) = 18432 floats = 73728 B = 72KB
    const int shmem = (16384 + PT * 64 + 512) * (int)sizeof(float);
    cudaFuncSetAttribute(proj_kernel, cudaFuncAttributeMaxDynamicSharedMemorySize, shmem);

    proj_kernel<<<444, 256, shmem>>>(x, w_proj, rs, ts);
    edge_pass1<<<(EE + 255) / 256, 256>>>(ei, elen, rds);
    // 8 lanes per edge: 4 edges per warp -> EE/4 warps
    edge_pass2<<<((EE / 4) * 32 + 255) / 256, 256>>>(ei);
    epilogue_kernel<<<(NN + 31) / 32, 256>>>(x, w_out, out);
}

// round 15
// speedup vs baseline: 1.2875x; 1.2875x over previous
#include <cuda_runtime.h>
#include <cuda_fp16.h>

#define NN 50000
#define EE 500000
#define FF 64
#define HH 4

// ---------------- scratch (device globals; no allocation allowed) ----------------
__device__ __align__(16) __half2 g_projh[(size_t)NN * 128]; // [n][h][f] fp16, 25.6 MB
__device__ __align__(16) float2  g_psum2[(size_t)NN * 32];  // [n][f] fp32 sum over heads, 12.8 MB
__device__ __align__(16) float g_sc[NN * 8];                // node scores [rad h0..3, tan h0..3]
__device__ __align__(16) float g_ssum[NN * 8];              // softmax denominators
__device__ __align__(16) float g_ex[(size_t)EE * 8];        // per-edge exp(logit)
__device__ __align__(16) float g_acc[NN * FF];              // scattered messages (head-mean folded)

__device__ __forceinline__ void red_add_v4(float* p, float4 v) {
    asm volatile("red.global.add.v4.f32 [%0], {%1,%2,%3,%4};"
                 :: "l"(p), "f"(v.x), "f"(v.y), "f"(v.z), "f"(v.w) : "memory");
}

// packed fp32 FMA: d = a*b + c  (2 lanes per instruction, FFMA2)
__device__ __forceinline__ float2 fma2(float2 a, float2 b, float2 c) {
    float2 d;
    asm("fma.rn.f32x2 %0, %1, %2, %3;"
        : "=l"(reinterpret_cast<unsigned long long&>(d))
        : "l"(reinterpret_cast<unsigned long long&>(a)),
          "l"(reinterpret_cast<unsigned long long&>(b)),
          "l"(reinterpret_cast<unsigned long long&>(c)));
    return d;
}

// ---------------- init: zero accumulators ----------------
__global__ void init_kernel() {
    int i = blockIdx.x * blockDim.x + threadIdx.x;
    int stride = gridDim.x * blockDim.x;
    for (int j = i; j < NN * FF; j += stride) g_acc[j] = 0.f;
    for (int j = i; j < NN * 8; j += stride) g_ssum[j] = 0.f;
}

// ---------------- per-node projection (fp16 out + fp32 head-sum) + node scores ----------
// EXACT R5 version (measured: 63.7us, best proj-with-sc across 10 rounds)
// proj[n,h,g] = sum_f x[n,f] * w_proj[h,f,g]     -> g_projh (fp16), g_psum2 (fp32 sum_h)
// sc[n,i]     = sum_f x[n,f] * wrt[i,f],  wrt[i,f] = sum_g w_proj[h,f,g]*score[h,g]
#define PT 32  // nodes per tile
__global__ void proj_kernel(const float* __restrict__ x,
                            const float* __restrict__ w_proj,
                            const float* __restrict__ rs,
                            const float* __restrict__ ts) {
    extern __shared__ float sh[];
    float2* wsh2 = (float2*)sh;          // [64][128] pairs: wsh2[f*128 + h*32 + gp] = w[h,f,2gp..2gp+1]
    float*  xs   = sh + 64 * 256;        // [PT][65] padded
    float*  wrt  = xs + PT * 65;         // [8][65]  padded

    int tid = threadIdx.x;

    // load weights as float2 pairs, transposed to [f][h*32+gp]
    for (int idx = tid; idx < 64 * 128; idx += 256) {
        int f = idx >> 7, p = idx & 127;
        int h = p >> 5, gp = p & 31;
        wsh2[idx] = ((const float2*)w_proj)[h * 2048 + f * 32 + gp];
    }
    __syncthreads();

    // wrt[i][f]
    for (int e = tid; e < 8 * 64; e += 256) {
        int i = e >> 6, f = e & 63;
        int h = i & 3;
        const float* sc = (i < 4) ? rs : ts;
        float s = 0.f;
        #pragma unroll 8
        for (int gp = 0; gp < 32; gp++) {
            float2 w = wsh2[f * 128 + h * 32 + gp];
            s += w.x * sc[h * 64 + 2 * gp] + w.y * sc[h * 64 + 2 * gp + 1];
        }
        wrt[i * 65 + f] = s;
    }

    int pg = tid & 31;       // g-pair column (covers g = 2pg, 2pg+1 of every head)
    int ng = tid >> 5;       // node group (4 nodes each)
    int ntiles = (NN + PT - 1) / PT;

    for (int tile = blockIdx.x; tile < ntiles; tile += gridDim.x) {
        int n0 = tile * PT;
        __syncthreads();  // orders wrt/xs across tiles
        for (int idx = tid; idx < PT * 64; idx += 256) {
            int nd = idx >> 6, f = idx & 63;
            int n = n0 + nd;
            xs[nd * 65 + f] = (n < NN) ? x[n * 64 + f] : 0.f;
        }
        __syncthreads();

        float2 acc[4][4];  // [node j][head h] — pair (2pg,2pg+1)
        #pragma unroll
        for (int j = 0; j < 4; j++)
            #pragma unroll
            for (int h = 0; h < 4; h++) acc[j][h] = make_float2(0.f, 0.f);

        #pragma unroll 4
        for (int f = 0; f < 64; f++) {
            float2 w0 = wsh2[f * 128 + pg];
            float2 w1 = wsh2[f * 128 + 32 + pg];
            float2 w2 = wsh2[f * 128 + 64 + pg];
            float2 w3 = wsh2[f * 128 + 96 + pg];
            #pragma unroll
            for (int j = 0; j < 4; j++) {
                float xv = xs[(ng * 4 + j) * 65 + f];
                float2 xx = make_float2(xv, xv);
                acc[j][0] = fma2(w0, xx, acc[j][0]);
                acc[j][1] = fma2(w1, xx, acc[j][1]);
                acc[j][2] = fma2(w2, xx, acc[j][2]);
                acc[j][3] = fma2(w3, xx, acc[j][3]);
            }
        }

        #pragma unroll
        for (int j = 0; j < 4; j++) {
            int n = n0 + ng * 4 + j;
            if (n < NN) {
                __half2* op = g_projh + (size_t)n * 128;   // [h*32 + pg]
                op[pg]      = __float22half2_rn(acc[j][0]);
                op[32 + pg] = __float22half2_rn(acc[j][1]);
                op[64 + pg] = __float22half2_rn(acc[j][2]);
                op[96 + pg] = __float22half2_rn(acc[j][3]);
                float2 ps;
                ps.x = acc[j][0].x + acc[j][1].x + acc[j][2].x + acc[j][3].x;
                ps.y = acc[j][0].y + acc[j][1].y + acc[j][2].y + acc[j][3].y;
                g_psum2[(size_t)n * 32 + pg] = ps;
            }
        }

        // node scores: thread -> (node tid/8, score-index tid%8)
        int nd2 = tid >> 3, i2 = tid & 7;
        int n2 = n0 + nd2;
        if (n2 < NN) {
            float s = 0.f;
            #pragma unroll 8
            for (int f = 0; f < 64; f++) s += xs[nd2 * 65 + f] * wrt[i2 * 65 + f];
            g_sc[n2 * 8 + i2] = s;
        }
    }
}

// ---------------- edge pass 1: exp(logits), accumulate softmax sums ----------------
__global__ void edge_pass1(const int* __restrict__ ei,
                           const float* __restrict__ elen,
                           const float* __restrict__ rds) {
    int i = blockIdx.x * blockDim.x + threadIdx.x;
    if (i >= EE) return;
    float scale = rds[0];
    int s = ei[i], r = ei[EE + i];
    const float4* scp = (const float4*)g_sc;
    float4 a0 = scp[s * 2], a1 = scp[s * 2 + 1];
    float4 b0 = scp[r * 2], b1 = scp[r * 2 + 1];
    float d = scale * elen[i];
    float4 er, et;
    er.x = __expf(a0.x - b0.x - d); er.y = __expf(a0.y - b0.y - d);
    er.z = __expf(a0.z - b0.z - d); er.w = __expf(a0.w - b0.w - d);
    et.x = __expf(a1.x - b1.x);     et.y = __expf(a1.y - b1.y);
    et.z = __expf(a1.z - b1.z);     et.w = __expf(a1.w - b1.w);
    float4* exp_ptr = (float4*)(g_ex + (size_t)i * 8);
    exp_ptr[0] = er;
    exp_ptr[1] = et;
    red_add_v4(g_ssum + r * 8, er);
    red_add_v4(g_ssum + r * 8 + 4, et);
}

// ---------------- edge pass 2: alpha-weighted scatter of fp16 sender proj ------------
// EXACT R6 version (measured 43.5-44.2us, best pass2 across all rounds):
// 8 lanes per edge (4 edges per warp); lane sub handles f-chunk [8sub, 8sub+7] of
// every head via one LDG.128 per head.
__global__ void edge_pass2(const int* __restrict__ ei) {
    int lane = threadIdx.x & 31;
    int warp = (blockIdx.x * blockDim.x + threadIdx.x) >> 5;
    int grp = lane >> 3, sub = lane & 7;
    int e = warp * 4 + grp;
    if (e >= EE) return;
    int s = ei[e], r = ei[EE + e];

    // every lane computes one of the 8 alphas
    float a = __fdividef(g_ex[(size_t)e * 8 + sub], g_ssum[r * 8 + sub]);
    // combined per-head weight = alpha_rad[h] + alpha_tan[h]  (shuffle within 8-lane group)
    const unsigned m = 0xffffffffu;
    float w0 = __shfl_sync(m, a, 0, 8) + __shfl_sync(m, a, 4, 8);
    float w1 = __shfl_sync(m, a, 1, 8) + __shfl_sync(m, a, 5, 8);
    float w2 = __shfl_sync(m, a, 2, 8) + __shfl_sync(m, a, 6, 8);
    float w3 = __shfl_sync(m, a, 3, 8) + __shfl_sync(m, a, 7, 8);

    // fp16 row: 256 halves = 32 uint4; head h occupies uint4 [h*8, h*8+7]
    const uint4* ph = (const uint4*)g_projh + (size_t)s * 32;
    uint4 q0 = ph[sub], q1 = ph[8 + sub], q2 = ph[16 + sub], q3 = ph[24 + sub];

    float v[8];
    #pragma unroll
    for (int k = 0; k < 8; k++) v[k] = 0.f;

    #pragma unroll
    for (int h = 0; h < 4; h++) {
        uint4 q = (h == 0) ? q0 : (h == 1) ? q1 : (h == 2) ? q2 : q3;
        float w = (h == 0) ? w0 : (h == 1) ? w1 : (h == 2) ? w2 : w3;
        float2 c0 = __half22float2(*(const __half2*)&q.x);
        float2 c1 = __half22float2(*(const __half2*)&q.y);
        float2 c2 = __half22float2(*(const __half2*)&q.z);
        float2 c3 = __half22float2(*(const __half2*)&q.w);
        v[0] += w * c0.x; v[1] += w * c0.y;
        v[2] += w * c1.x; v[3] += w * c1.y;
        v[4] += w * c2.x; v[5] += w * c2.y;
        v[6] += w * c3.x; v[7] += w * c3.y;
    }
    // 0.25 = head mean, applied once here
    float4 vA = make_float4(0.25f * v[0], 0.25f * v[1], 0.25f * v[2], 0.25f * v[3]);
    float4 vB = make_float4(0.25f * v[4], 0.25f * v[5], 0.25f * v[6], 0.25f * v[7]);
    float* dst = g_acc + r * 64 + sub * 8;
    red_add_v4(dst, vA);
    red_add_v4(dst + 4, vB);
}

// ---------------- epilogue: msg, residual + out-GEMM (packed f32x2) ----------------
// EXACT R5 version. warp handles 4 nodes; lane handles output-column pair.
// msg[n,f] = g_acc[n,f] - 0.5*flag*psum[n,f]
__global__ void epilogue_kernel(const float* __restrict__ x,
                                const float* __restrict__ w_out,
                                float* __restrict__ out) {
    __shared__ float2 wsh2[64 * 32];     // [f][gp]
    __shared__ float msh[8][4][64];
    int tid = threadIdx.x, lane = tid & 31, wid = tid >> 5;
    for (int idx = tid; idx < 2048; idx += 256) wsh2[idx] = ((const float2*)w_out)[idx];
    __syncthreads();

    int base = (blockIdx.x * 8 + wid) * 4;
    if (base >= NN) return;

    const float* psum = (const float*)g_psum2;
    #pragma unroll
    for (int j = 0; j < 4; j++) {
        int n = base + j;
        if (n >= NN) { msh[wid][j][lane] = 0.f; msh[wid][j][lane + 32] = 0.f; continue; }
        float ne = (g_ssum[n * 8] > 0.f) ? 0.5f : 0.f;
        #pragma unroll
        for (int k = 0; k < 2; k++) {
            int f = lane + k * 32;
            msh[wid][j][f] = g_acc[n * 64 + f] - ne * psum[(size_t)n * 64 + f];
        }
    }
    __syncwarp();

    float2 a2[4];
    #pragma unroll
    for (int j = 0; j < 4; j++) {
        int n = base + j;
        a2[j] = (n < NN) ? ((const float2*)x)[n * 32 + lane] : make_float2(0.f, 0.f);
    }
    #pragma unroll 4
    for (int f = 0; f < 64; f++) {
        float2 w = wsh2[f * 32 + lane];
        #pragma unroll
        for (int j = 0; j < 4; j++) {
            float m = msh[wid][j][f];
            a2[j] = fma2(w, make_float2(m, m), a2[j]);
        }
    }
    #pragma unroll
    for (int j = 0; j < 4; j++) {
        int n = base + j;
        if (n < NN) ((float2*)out)[n * 32 + lane] = a2[j];
    }
}

// ---------------- launch ----------------
extern "C" void kernel_launch(void* const* d_in, const int* in_sizes, int n_in,
                              void* d_out, int out_size) {
    const float* x      = (const float*)d_in[0];
    const int*   ei     = (const int*)d_in[1];
    // d_in[2] = edge_vec (unused by reference)
    const float* elen   = (const float*)d_in[3];
    const float* w_proj = (const float*)d_in[4];
    const float* rs     = (const float*)d_in[5];
    const float* ts     = (const float*)d_in[6];
    const float* rds    = (const float*)d_in[7];
    const float* w_out  = (const float*)d_in[8];
    float* out = (float*)d_out;

    const int shmem = (64 * 256 + PT * 65 + 8 * 65) * (int)sizeof(float);  // 75,936 B
    cudaFuncSetAttribute(proj_kernel, cudaFuncAttributeMaxDynamicSharedMemorySize, shmem);

    init_kernel<<<512, 256>>>();
    proj_kernel<<<296, 256, shmem>>>(x, w_proj, rs, ts);
    edge_pass1<<<(EE + 255) / 256, 256>>>(ei, elen, rds);
    // 8 lanes per edge: 4 edges per warp -> EE/4 warps
    edge_pass2<<<((EE / 4) * 32 + 255) / 256, 256>>>(ei);
    epilogue_kernel<<<(NN + 31) / 32, 256>>>(x, w_out, out);
}